// round 6
// baseline (speedup 1.0000x reference)
#include <cuda_runtime.h>
#include <cuda_bf16.h>
#include <cstdint>

#define MM 16384
#define DD 1024
#define NN 1024
#define KCP 34

// Split-bf16 operands: [row][kblock(32)][32 hi | 32 lo] bf16
__device__ __nv_bfloat16 A2_buf[(size_t)MM * 2 * DD];   // 64 MB
__device__ __nv_bfloat16 B2_buf[(size_t)NN * 2 * DD];   // 4 MB (B transposed to [n][k])

__device__ __forceinline__ uint32_t s2u(const void* p) {
    uint32_t a;
    asm("{ .reg .u64 t; cvta.to.shared.u64 t, %1; cvt.u32.u64 %0, t; }" : "=r"(a) : "l"(p));
    return a;
}

#define LDSM4(r, a) \
    asm volatile("ldmatrix.sync.aligned.m8n8.x4.shared.b16 {%0,%1,%2,%3}, [%4];" \
                 : "=r"((r)[0]), "=r"((r)[1]), "=r"((r)[2]), "=r"((r)[3]) : "r"(a))

#define MMA16816(c, a, b0, b1) \
    asm volatile("mma.sync.aligned.m16n8k16.row.col.f32.bf16.bf16.f32 " \
                 "{%0,%1,%2,%3}, {%4,%5,%6,%7}, {%8,%9}, {%0,%1,%2,%3};" \
                 : "+f"((c).x), "+f"((c).y), "+f"((c).z), "+f"((c).w) \
                 : "r"((a)[0]), "r"((a)[1]), "r"((a)[2]), "r"((a)[3]), "r"(b0), "r"(b1))

#define CPASYNC16(d, s) \
    asm volatile("cp.async.cg.shared.global [%0], [%1], 16;" :: "r"(d), "l"(s))

// ---------------- convert kernels ----------------
__global__ __launch_bounds__(256) void convert_A(const float* __restrict__ X) {
    int t = blockIdx.x * blockDim.x + threadIdx.x;     // MM*DD/2 threads
    int m = t >> 9;
    int k = (t & 511) * 2;
    float2 v = *reinterpret_cast<const float2*>(X + (size_t)m * DD + k);
    __nv_bfloat16 h0 = __float2bfloat16(v.x);
    __nv_bfloat16 h1 = __float2bfloat16(v.y);
    __nv_bfloat16 l0 = __float2bfloat16(v.x - __bfloat162float(h0));
    __nv_bfloat16 l1 = __float2bfloat16(v.y - __bfloat162float(h1));
    int kb = k >> 5, j = k & 31;
    size_t base = ((size_t)m * 32 + kb) * 64;
    __nv_bfloat162 hh; hh.x = h0; hh.y = h1;
    __nv_bfloat162 ll; ll.x = l0; ll.y = l1;
    *reinterpret_cast<__nv_bfloat162*>(A2_buf + base + j)      = hh;
    *reinterpret_cast<__nv_bfloat162*>(A2_buf + base + 32 + j) = ll;
}

__global__ __launch_bounds__(256) void convert_B(const float* __restrict__ W) {
    int t = blockIdx.x * blockDim.x + threadIdx.x;     // DD*NN threads
    int k = t >> 10;
    int n = t & 1023;
    float v = W[(size_t)k * NN + n];
    __nv_bfloat16 h = __float2bfloat16(v);
    __nv_bfloat16 l = __float2bfloat16(v - __bfloat162float(h));
    int kb = k >> 5, j = k & 31;
    size_t base = ((size_t)n * 32 + kb) * 64;
    B2_buf[base + j]      = h;
    B2_buf[base + 32 + j] = l;
}

// ---------------- fused GEMM + spline ----------------
#define STAGE_BYTES 18432          // 128 rows * 144 B (128 data + 16 pad)
#define SOFF_STAGES 17920
#define SMEM_TOTAL  (SOFF_STAGES + 8 * STAGE_BYTES)   // 165376

__device__ __forceinline__ float spline_eval(float s, const float* __restrict__ q)
{
    float t = s * 4.0f;
    float u = t - floorf(t);
    float pf = floorf((s + 4.0f) * 3.75f + 1.0f);
    if (s <= -4.0f) pf = 1.0f;
    if (s >=  4.0f) pf = 31.0f;
    int p0 = (int)pf;
    p0 = max(1, min(31, p0));
    float Q0 = q[p0 - 1];
    float Q1 = q[p0];
    float Q2 = q[p0 + 1];
    float Q3 = q[p0 + 2];
    float c3 = 3.0f * (Q1 - Q2) + (Q3 - Q0);
    float c2 = 2.0f * Q0 - 5.0f * Q1 + 4.0f * Q2 - Q3;
    float c1 = Q2 - Q0;
    float c0 = 2.0f * Q1;
    return 0.5f * (((c3 * u + c2) * u + c1) * u + c0);
}

__device__ __forceinline__ void load_stage(uint32_t aBase, uint32_t bBase, int s, int c,
                                           const __nv_bfloat16* Ag, const __nv_bfloat16* Bg,
                                           int tid)
{
    const uint32_t dA = aBase + s * STAGE_BYTES;
    const uint32_t dB = bBase + s * STAGE_BYTES;
    #pragma unroll
    for (int i = 0; i < 4; ++i) {
        int chunk = tid + i * 256;
        int r = chunk >> 3, col = chunk & 7;
        const size_t src = (size_t)r * 2048 + (size_t)c * 64 + col * 8;
        CPASYNC16(dA + r * 144 + col * 16, (const char*)(Ag + src));
        CPASYNC16(dB + r * 144 + col * 16, (const char*)(Bg + src));
    }
}

__global__ __launch_bounds__(256, 1) void gemm_spline(const float* __restrict__ CP,
                                                      float* __restrict__ out)
{
    extern __shared__ char smem[];
    float* cps = reinterpret_cast<float*>(smem);
    const uint32_t su = s2u(smem);
    const uint32_t aBase = su + SOFF_STAGES;
    const uint32_t bBase = su + SOFF_STAGES + 4 * STAGE_BYTES;

    const int tid  = threadIdx.x;
    const int lane = tid & 31;
    const int wid  = tid >> 5;
    const int bx = blockIdx.x;   // n tile (0..7)
    const int by = blockIdx.y;   // m tile (0..127)

    // stage control points (128 neurons, padded stride 35)
    for (int i = tid; i < 128 * KCP; i += 256) {
        int c = i / KCP, k = i - c * KCP;
        cps[c * 35 + k] = CP[(size_t)(bx * 128 + c) * KCP + k];
    }

    const __nv_bfloat16* Ag = A2_buf + (size_t)by * 128 * 2048;
    const __nv_bfloat16* Bg = B2_buf + (size_t)bx * 128 * 2048;

    // prologue: stages 0..2
    #pragma unroll
    for (int c = 0; c < 3; ++c) {
        load_stage(aBase, bBase, c, c, Ag, Bg, tid);
        asm volatile("cp.async.commit_group;" ::: "memory");
    }

    float4 acc[4][4];
    #pragma unroll
    for (int i = 0; i < 4; ++i)
        #pragma unroll
        for (int j = 0; j < 4; ++j)
            acc[i][j] = make_float4(0.f, 0.f, 0.f, 0.f);

    const int mw = (wid >> 2) * 64;
    const int nw = (wid & 3) * 32;
    const int lrow = lane & 15;
    const int lcol = lane >> 4;

    #pragma unroll 1
    for (int c = 0; c < 32; ++c) {
        asm volatile("cp.async.wait_group 2;" ::: "memory");
        __syncthreads();
        if (c + 3 < 32)
            load_stage(aBase, bBase, (c + 3) & 3, c + 3, Ag, Bg, tid);
        asm volatile("cp.async.commit_group;" ::: "memory");

        const int s = c & 3;
        const uint32_t aRow = aBase + s * STAGE_BYTES + (mw + lrow) * 144 + lcol * 16;
        const uint32_t bRow = bBase + s * STAGE_BYTES + (nw + lrow) * 144 + lcol * 16;

        #pragma unroll
        for (int ks = 0; ks < 2; ++ks) {
            uint32_t Ah[4][4], Al[4][4], Bh[2][4], Bl[2][4];
            #pragma unroll
            for (int mf = 0; mf < 4; ++mf) {
                LDSM4(Ah[mf], aRow + mf * (16 * 144) + ks * 32);
                LDSM4(Al[mf], aRow + mf * (16 * 144) + ks * 32 + 64);
            }
            #pragma unroll
            for (int g = 0; g < 2; ++g) {
                LDSM4(Bh[g], bRow + g * (16 * 144) + ks * 32);
                LDSM4(Bl[g], bRow + g * (16 * 144) + ks * 32 + 64);
            }
            // Term-outermost order: same-accumulator MMAs are 16 issues apart,
            // hiding HMMA accumulator RAW latency. 4 terms incl. lo*lo.
            #pragma unroll
            for (int term = 0; term < 4; ++term) {
                #pragma unroll
                for (int mf = 0; mf < 4; ++mf)
                    #pragma unroll
                    for (int nf = 0; nf < 4; ++nf) {
                        const int g = nf >> 1, w = nf & 1;
                        if (term == 0)
                            MMA16816(acc[mf][nf], Ah[mf], Bh[g][w], Bh[g][w + 2]);
                        else if (term == 1)
                            MMA16816(acc[mf][nf], Al[mf], Bh[g][w], Bh[g][w + 2]);
                        else if (term == 2)
                            MMA16816(acc[mf][nf], Ah[mf], Bl[g][w], Bl[g][w + 2]);
                        else
                            MMA16816(acc[mf][nf], Al[mf], Bl[g][w], Bl[g][w + 2]);
                    }
            }
        }
    }

    // epilogue: spline + store
    #pragma unroll
    for (int mf = 0; mf < 4; ++mf) {
        const int row0 = mw + mf * 16 + (lane >> 2);
        const size_t g0 = (size_t)(by * 128 + row0) * NN + bx * 128;
        const size_t g1 = g0 + 8 * NN;
        #pragma unroll
        for (int nf = 0; nf < 4; ++nf) {
            const int cl = nw + nf * 8 + 2 * (lane & 3);
            const float* q0 = &cps[cl * 35];
            const float* q1 = &cps[(cl + 1) * 35];
            float2 o0, o1;
            o0.x = spline_eval(acc[mf][nf].x, q0);
            o0.y = spline_eval(acc[mf][nf].y, q1);
            o1.x = spline_eval(acc[mf][nf].z, q0);
            o1.y = spline_eval(acc[mf][nf].w, q1);
            *reinterpret_cast<float2*>(out + g0 + cl) = o0;
            *reinterpret_cast<float2*>(out + g1 + cl) = o1;
        }
    }
}

extern "C" void kernel_launch(void* const* d_in, const int* in_sizes, int n_in,
                              void* d_out, int out_size)
{
    const float* X  = (const float*)d_in[0];
    const float* W  = (const float*)d_in[1];
    const float* CP = (const float*)d_in[2];
    float* out = (float*)d_out;

    cudaFuncSetAttribute(gemm_spline, cudaFuncAttributeMaxDynamicSharedMemorySize, SMEM_TOTAL);

    convert_A<<<(MM * DD / 2) / 256, 256>>>(X);
    convert_B<<<(DD * NN) / 256, 256>>>(W);

    dim3 grid(NN / 128, MM / 128);   // (8, 128)
    gemm_spline<<<grid, 256, SMEM_TOTAL>>>(CP, out);
}

// round 7
// speedup vs baseline: 1.3193x; 1.3193x over previous
#include <cuda_runtime.h>
#include <cuda_fp16.h>
#include <cstdint>

#define MM 16384
#define DD 1024
#define NN 1024
#define KCP 34

// Split-fp16 operands: [row][kblock(32)][32 hi | 32 lo] half
__device__ __half A2_buf[(size_t)MM * 2 * DD];   // 64 MB
__device__ __half B2_buf[(size_t)NN * 2 * DD];   // 4 MB (B transposed to [n][k])

__device__ __forceinline__ uint32_t s2u(const void* p) {
    uint32_t a;
    asm("{ .reg .u64 t; cvta.to.shared.u64 t, %1; cvt.u32.u64 %0, t; }" : "=r"(a) : "l"(p));
    return a;
}

#define LDSM4(r, a) \
    asm volatile("ldmatrix.sync.aligned.m8n8.x4.shared.b16 {%0,%1,%2,%3}, [%4];" \
                 : "=r"((r)[0]), "=r"((r)[1]), "=r"((r)[2]), "=r"((r)[3]) : "r"(a))

#define MMA16816(c, a, b0, b1) \
    asm volatile("mma.sync.aligned.m16n8k16.row.col.f32.f16.f16.f32 " \
                 "{%0,%1,%2,%3}, {%4,%5,%6,%7}, {%8,%9}, {%0,%1,%2,%3};" \
                 : "+f"((c).x), "+f"((c).y), "+f"((c).z), "+f"((c).w) \
                 : "r"((a)[0]), "r"((a)[1]), "r"((a)[2]), "r"((a)[3]), "r"(b0), "r"(b1))

#define CPASYNC16(d, s) \
    asm volatile("cp.async.cg.shared.global [%0], [%1], 16;" :: "r"(d), "l"(s))

// ---------------- convert kernels ----------------
__global__ __launch_bounds__(256) void convert_A(const float* __restrict__ X) {
    int t = blockIdx.x * blockDim.x + threadIdx.x;     // MM*DD/2 threads
    int m = t >> 9;
    int k = (t & 511) * 2;
    float2 v = *reinterpret_cast<const float2*>(X + (size_t)m * DD + k);
    __half h0 = __float2half_rn(v.x);
    __half h1 = __float2half_rn(v.y);
    __half l0 = __float2half_rn(v.x - __half2float(h0));
    __half l1 = __float2half_rn(v.y - __half2float(h1));
    int kb = k >> 5, j = k & 31;
    size_t base = ((size_t)m * 32 + kb) * 64;
    __half2 hh; hh.x = h0; hh.y = h1;
    __half2 ll; ll.x = l0; ll.y = l1;
    *reinterpret_cast<__half2*>(A2_buf + base + j)      = hh;
    *reinterpret_cast<__half2*>(A2_buf + base + 32 + j) = ll;
}

__global__ __launch_bounds__(256) void convert_B(const float* __restrict__ W) {
    int t = blockIdx.x * blockDim.x + threadIdx.x;     // DD*NN threads
    int k = t >> 10;
    int n = t & 1023;
    float v = W[(size_t)k * NN + n];
    __half h = __float2half_rn(v);
    __half l = __float2half_rn(v - __half2float(h));
    int kb = k >> 5, j = k & 31;
    size_t base = ((size_t)n * 32 + kb) * 64;
    B2_buf[base + j]      = h;
    B2_buf[base + 32 + j] = l;
}

// ---------------- fused GEMM + spline ----------------
// 2-stage pipeline, 2 CTAs/SM.
// SMEM: cps 128*35*4 = 17920, then 2 A stages (18432 each), 2 B stages.
#define STAGE_BYTES 18432          // 128 rows * 144 B (128 data + 16 pad)
#define SOFF_A      17920
#define SOFF_B      (17920 + 2 * STAGE_BYTES)
#define SMEM_TOTAL  (17920 + 4 * STAGE_BYTES)   // 91648 -> 2 CTAs/SM

__device__ __forceinline__ float spline_eval(float s, const float* __restrict__ q)
{
    float t = s * 4.0f;
    float u = t - floorf(t);
    float pf = floorf((s + 4.0f) * 3.75f + 1.0f);
    if (s <= -4.0f) pf = 1.0f;
    if (s >=  4.0f) pf = 31.0f;
    int p0 = (int)pf;
    p0 = max(1, min(31, p0));
    float Q0 = q[p0 - 1];
    float Q1 = q[p0];
    float Q2 = q[p0 + 1];
    float Q3 = q[p0 + 2];
    float c3 = 3.0f * (Q1 - Q2) + (Q3 - Q0);
    float c2 = 2.0f * Q0 - 5.0f * Q1 + 4.0f * Q2 - Q3;
    float c1 = Q2 - Q0;
    float c0 = 2.0f * Q1;
    return 0.5f * (((c3 * u + c2) * u + c1) * u + c0);
}

__device__ __forceinline__ void load_stage(uint32_t aBase, uint32_t bBase, int s, int c,
                                           const __half* Ag, const __half* Bg, int tid)
{
    const uint32_t dA = aBase + s * STAGE_BYTES;
    const uint32_t dB = bBase + s * STAGE_BYTES;
    #pragma unroll
    for (int i = 0; i < 4; ++i) {
        int chunk = tid + i * 256;
        int r = chunk >> 3, col = chunk & 7;
        const size_t src = (size_t)r * 2048 + (size_t)c * 64 + col * 8;
        CPASYNC16(dA + r * 144 + col * 16, (const char*)(Ag + src));
        CPASYNC16(dB + r * 144 + col * 16, (const char*)(Bg + src));
    }
}

__global__ __launch_bounds__(256, 2) void gemm_spline(const float* __restrict__ CP,
                                                      float* __restrict__ out)
{
    extern __shared__ char smem[];
    float* cps = reinterpret_cast<float*>(smem);
    const uint32_t su = s2u(smem);
    const uint32_t aBase = su + SOFF_A;
    const uint32_t bBase = su + SOFF_B;

    const int tid  = threadIdx.x;
    const int lane = tid & 31;
    const int wid  = tid >> 5;
    const int bx = blockIdx.x;   // n tile (0..7)
    const int by = blockIdx.y;   // m tile (0..127)

    // stage control points (128 neurons, padded stride 35)
    for (int i = tid; i < 128 * KCP; i += 256) {
        int c = i / KCP, k = i - c * KCP;
        cps[c * 35 + k] = CP[(size_t)(bx * 128 + c) * KCP + k];
    }

    const __half* Ag = A2_buf + (size_t)by * 128 * 2048;
    const __half* Bg = B2_buf + (size_t)bx * 128 * 2048;

    // prologue: stages 0,1
    load_stage(aBase, bBase, 0, 0, Ag, Bg, tid);
    asm volatile("cp.async.commit_group;" ::: "memory");
    load_stage(aBase, bBase, 1, 1, Ag, Bg, tid);
    asm volatile("cp.async.commit_group;" ::: "memory");

    float4 acc[4][4];
    #pragma unroll
    for (int i = 0; i < 4; ++i)
        #pragma unroll
        for (int j = 0; j < 4; ++j)
            acc[i][j] = make_float4(0.f, 0.f, 0.f, 0.f);

    const int mw = (wid >> 2) * 64;
    const int nw = (wid & 3) * 32;
    const int lrow = lane & 15;
    const int lcol = lane >> 4;

    #pragma unroll 1
    for (int c = 0; c < 32; ++c) {
        // One group was committed every iteration (possibly empty), so
        // wait_group 1 forces the load of chunk c complete (only chunk c+1's
        // group may still be pending).
        asm volatile("cp.async.wait_group 1;" ::: "memory");
        __syncthreads();

        const int s = c & 1;
        const uint32_t aRow = aBase + s * STAGE_BYTES + (mw + lrow) * 144 + lcol * 16;
        const uint32_t bRow = bBase + s * STAGE_BYTES + (nw + lrow) * 144 + lcol * 16;

        #pragma unroll
        for (int ks = 0; ks < 2; ++ks) {
            uint32_t Ah[4][4], Al[4][4], Bh[2][4], Bl[2][4];
            #pragma unroll
            for (int mf = 0; mf < 4; ++mf) {
                LDSM4(Ah[mf], aRow + mf * (16 * 144) + ks * 32);
                LDSM4(Al[mf], aRow + mf * (16 * 144) + ks * 32 + 64);
            }
            #pragma unroll
            for (int g = 0; g < 2; ++g) {
                LDSM4(Bh[g], bRow + g * (16 * 144) + ks * 32);
                LDSM4(Bl[g], bRow + g * (16 * 144) + ks * 32 + 64);
            }
            #pragma unroll
            for (int mf = 0; mf < 4; ++mf)
                #pragma unroll
                for (int nf = 0; nf < 4; ++nf) {
                    const int g = nf >> 1, w = nf & 1;
                    MMA16816(acc[mf][nf], Ah[mf], Bh[g][w], Bh[g][w + 2]);   // hi*hi
                    MMA16816(acc[mf][nf], Al[mf], Bh[g][w], Bh[g][w + 2]);   // lo*hi
                    MMA16816(acc[mf][nf], Ah[mf], Bl[g][w], Bl[g][w + 2]);   // hi*lo
                }
        }

        __syncthreads();   // all warps done with stage s before it is overwritten
        if (c + 2 < 32)
            load_stage(aBase, bBase, s, c + 2, Ag, Bg, tid);
        asm volatile("cp.async.commit_group;" ::: "memory");  // empty group at tail keeps the count honest
    }

    // epilogue: spline + store
    #pragma unroll
    for (int mf = 0; mf < 4; ++mf) {
        const int row0 = mw + mf * 16 + (lane >> 2);
        const size_t g0 = (size_t)(by * 128 + row0) * NN + bx * 128;
        const size_t g1 = g0 + 8 * NN;
        #pragma unroll
        for (int nf = 0; nf < 4; ++nf) {
            const int cl = nw + nf * 8 + 2 * (lane & 3);
            const float* q0 = &cps[cl * 35];
            const float* q1 = &cps[(cl + 1) * 35];
            float2 o0, o1;
            o0.x = spline_eval(acc[mf][nf].x, q0);
            o0.y = spline_eval(acc[mf][nf].y, q1);
            o1.x = spline_eval(acc[mf][nf].z, q0);
            o1.y = spline_eval(acc[mf][nf].w, q1);
            *reinterpret_cast<float2*>(out + g0 + cl) = o0;
            *reinterpret_cast<float2*>(out + g1 + cl) = o1;
        }
    }
}

extern "C" void kernel_launch(void* const* d_in, const int* in_sizes, int n_in,
                              void* d_out, int out_size)
{
    const float* X  = (const float*)d_in[0];
    const float* W  = (const float*)d_in[1];
    const float* CP = (const float*)d_in[2];
    float* out = (float*)d_out;

    cudaFuncSetAttribute(gemm_spline, cudaFuncAttributeMaxDynamicSharedMemorySize, SMEM_TOTAL);

    convert_A<<<(MM * DD / 2) / 256, 256>>>(X);
    convert_B<<<(DD * NN) / 256, 256>>>(W);

    dim3 grid(NN / 128, MM / 128);   // (8, 128)
    gemm_spline<<<grid, 256, SMEM_TOTAL>>>(CP, out);
}

// round 8
// speedup vs baseline: 1.4970x; 1.1347x over previous
#include <cuda_runtime.h>
#include <cuda_fp16.h>
#include <cstdint>

#define MM 16384
#define DD 1024
#define NN 1024
#define KCP 34

// Chunk-contiguous, XOR-swizzled split-fp16 operands.
// A3: [mtile(128)][chunk(32)][16KB tile]; tile = 128 rows x 128B.
//   row r: granules g0..g7 (16B each) stored at (g ^ (r&7))*16.
//   g0..3 = hi halves k0..31, g4..7 = lo halves.
// B3: [ntile(8)][chunk(32)][16KB tile], same structure over n-rows.
__device__ __half A3_buf[(size_t)MM * 2 * DD];   // 64 MB
__device__ __half B3_buf[(size_t)NN * 2 * DD];   // 4 MB

__device__ __forceinline__ uint32_t s2u(const void* p) {
    uint32_t a;
    asm("{ .reg .u64 t; cvta.to.shared.u64 t, %1; cvt.u32.u64 %0, t; }" : "=r"(a) : "l"(p));
    return a;
}

#define LDSM4(r, a) \
    asm volatile("ldmatrix.sync.aligned.m8n8.x4.shared.b16 {%0,%1,%2,%3}, [%4];" \
                 : "=r"((r)[0]), "=r"((r)[1]), "=r"((r)[2]), "=r"((r)[3]) : "r"(a))

#define MMA16816(c, a, b0, b1) \
    asm volatile("mma.sync.aligned.m16n8k16.row.col.f32.f16.f16.f32 " \
                 "{%0,%1,%2,%3}, {%4,%5,%6,%7}, {%8,%9}, {%0,%1,%2,%3};" \
                 : "+f"((c).x), "+f"((c).y), "+f"((c).z), "+f"((c).w) \
                 : "r"((a)[0]), "r"((a)[1]), "r"((a)[2]), "r"((a)[3]), "r"(b0), "r"(b1))

// ---------------- fused convert kernel ----------------
#define A_BLOCKS 32768             // (MM*DD/2)/256
#define B_BLOCKS 4096              // (DD*NN)/256

__global__ __launch_bounds__(256) void convert_fused(const float* __restrict__ X,
                                                     const float* __restrict__ W)
{
    int b = blockIdx.x;
    if (b < A_BLOCKS) {
        int t = b * 256 + threadIdx.x;
        int m = t >> 9;
        int k = (t & 511) * 2;
        float2 v = *reinterpret_cast<const float2*>(X + (size_t)m * DD + k);
        __half h0 = __float2half_rn(v.x);
        __half h1 = __float2half_rn(v.y);
        __half l0 = __float2half_rn(v.x - __half2float(h0));
        __half l1 = __float2half_rn(v.y - __half2float(h1));
        int tile = m >> 7, r = m & 127, kb = k >> 5;
        char* base = reinterpret_cast<char*>(A3_buf + ((size_t)(tile * 32 + kb)) * 8192);
        int gh = (k & 31) >> 3;
        int xk = r & 7;
        int woff = (k & 7) * 2;
        uint32_t offh = (uint32_t)(r * 128 + ((gh ^ xk) * 16) + woff);
        uint32_t offl = (uint32_t)(r * 128 + (((gh + 4) ^ xk) * 16) + woff);
        __half2 hh; hh.x = h0; hh.y = h1;
        __half2 ll; ll.x = l0; ll.y = l1;
        *reinterpret_cast<__half2*>(base + offh) = hh;
        *reinterpret_cast<__half2*>(base + offl) = ll;
    } else {
        int t = (b - A_BLOCKS) * 256 + threadIdx.x;
        int k = t >> 10;
        int n = t & 1023;
        float v = W[(size_t)k * NN + n];
        __half h = __float2half_rn(v);
        __half l = __float2half_rn(v - __half2float(h));
        int tile = n >> 7, r = n & 127, kb = k >> 5;
        char* base = reinterpret_cast<char*>(B3_buf + ((size_t)(tile * 32 + kb)) * 8192);
        int gh = (k & 31) >> 3;
        int xk = r & 7;
        int woff = (k & 7) * 2;
        *reinterpret_cast<__half*>(base + r * 128 + ((gh ^ xk) * 16) + woff)       = h;
        *reinterpret_cast<__half*>(base + r * 128 + (((gh + 4) ^ xk) * 16) + woff) = l;
    }
}

// ---------------- fused GEMM + spline ----------------
// SMEM: cps 128*35*4 = 17920 | 2 A stages 16KB | 2 B stages 16KB  -> 83456 B, 2 CTAs/SM
#define TILE_BYTES  16384
#define SOFF_A      17920
#define SOFF_B      (17920 + 2 * TILE_BYTES)
#define SOFF_MBAR   (17920 + 4 * TILE_BYTES)          // 2 x 8B mbarriers
#define SMEM_TOTAL  (17920 + 4 * TILE_BYTES + 64)     // 83520

__device__ __forceinline__ float spline_eval(float s, const float* __restrict__ q)
{
    float t = s * 4.0f;
    float u = t - floorf(t);
    float pf = floorf((s + 4.0f) * 3.75f + 1.0f);
    if (s <= -4.0f) pf = 1.0f;
    if (s >=  4.0f) pf = 31.0f;
    int p0 = (int)pf;
    p0 = max(1, min(31, p0));
    float Q0 = q[p0 - 1];
    float Q1 = q[p0];
    float Q2 = q[p0 + 1];
    float Q3 = q[p0 + 2];
    float c3 = 3.0f * (Q1 - Q2) + (Q3 - Q0);
    float c2 = 2.0f * Q0 - 5.0f * Q1 + 4.0f * Q2 - Q3;
    float c1 = Q2 - Q0;
    float c0 = 2.0f * Q1;
    return 0.5f * (((c3 * u + c2) * u + c1) * u + c0);
}

__device__ __forceinline__ void mbar_init(uint32_t mbar, uint32_t cnt) {
    asm volatile("mbarrier.init.shared.b64 [%0], %1;" :: "r"(mbar), "r"(cnt) : "memory");
}
__device__ __forceinline__ void mbar_expect(uint32_t mbar, uint32_t bytes) {
    asm volatile("mbarrier.arrive.expect_tx.shared.b64 _, [%0], %1;" :: "r"(mbar), "r"(bytes) : "memory");
}
__device__ __forceinline__ void mbar_wait(uint32_t mbar, uint32_t parity) {
    asm volatile(
        "{\n\t.reg .pred P;\n\t"
        "LW%=:\n\t"
        "mbarrier.try_wait.parity.acquire.cta.shared::cta.b64 P, [%0], %1, 0x989680;\n\t"
        "@P bra.uni LD%=;\n\t"
        "bra.uni LW%=;\n\t"
        "LD%=:\n\t}"
        :: "r"(mbar), "r"(parity) : "memory");
}
__device__ __forceinline__ void bulk_g2s(uint32_t dst, const void* src, uint32_t bytes, uint32_t mbar) {
    asm volatile("cp.async.bulk.shared::cluster.global.mbarrier::complete_tx::bytes [%0], [%1], %2, [%3];"
                 :: "r"(dst), "l"(src), "r"(bytes), "r"(mbar) : "memory");
}

__global__ __launch_bounds__(256, 2) void gemm_spline(const float* __restrict__ CP,
                                                      float* __restrict__ out)
{
    extern __shared__ char smem[];
    float* cps = reinterpret_cast<float*>(smem);
    const uint32_t su = s2u(smem);
    const uint32_t MBAR = su + SOFF_MBAR;

    const int tid  = threadIdx.x;
    const int lane = tid & 31;
    const int wid  = tid >> 5;
    const int bx = blockIdx.x;   // n tile (0..7)
    const int by = blockIdx.y;   // m tile (0..127)

    const char* Ag = reinterpret_cast<const char*>(A3_buf) + (size_t)by * 32 * TILE_BYTES;
    const char* Bg = reinterpret_cast<const char*>(B3_buf) + (size_t)bx * 32 * TILE_BYTES;

    if (tid == 0) {
        mbar_init(MBAR + 0, 1);
        mbar_init(MBAR + 8, 1);
        asm volatile("fence.proxy.async;" ::: "memory");
        // prologue: load chunks 0,1 into stages 0,1
        #pragma unroll
        for (int s = 0; s < 2; ++s) {
            mbar_expect(MBAR + 8 * s, 2 * TILE_BYTES);
            bulk_g2s(su + SOFF_A + s * TILE_BYTES, Ag + (size_t)s * TILE_BYTES, TILE_BYTES, MBAR + 8 * s);
            bulk_g2s(su + SOFF_B + s * TILE_BYTES, Bg + (size_t)s * TILE_BYTES, TILE_BYTES, MBAR + 8 * s);
        }
    }

    // stage control points (128 neurons, padded stride 35)
    for (int i = tid; i < 128 * KCP; i += 256) {
        int c = i / KCP, k = i - c * KCP;
        cps[c * 35 + k] = CP[(size_t)(bx * 128 + c) * KCP + k];
    }
    __syncthreads();   // mbarrier init + cps visible to all

    float4 acc[4][4];
    #pragma unroll
    for (int i = 0; i < 4; ++i)
        #pragma unroll
        for (int j = 0; j < 4; ++j)
            acc[i][j] = make_float4(0.f, 0.f, 0.f, 0.f);

    const int mw = (wid >> 2) * 64;
    const int nw = (wid & 3) * 32;
    const int lrow = lane & 15;
    const int lcol = lane >> 4;
    const int xk = lrow & 7;     // swizzle key (mw, nw are multiples of 8)

    #pragma unroll 1
    for (int c = 0; c < 32; ++c) {
        const int s = c & 1;
        mbar_wait(MBAR + 8 * s, (c >> 1) & 1);

        const uint32_t aRow = su + SOFF_A + s * TILE_BYTES + (mw + lrow) * 128;
        const uint32_t bRow = su + SOFF_B + s * TILE_BYTES + (nw + lrow) * 128;

        #pragma unroll
        for (int ks = 0; ks < 2; ++ks) {
            uint32_t Ah[4][4], Al[4][4], Bh[2][4], Bl[2][4];
            const uint32_t gh = (uint32_t)(((2 * ks + lcol) ^ xk) * 16);
            const uint32_t gl = (uint32_t)((((2 * ks + lcol) + 4) ^ xk) * 16);
            #pragma unroll
            for (int mf = 0; mf < 4; ++mf) {
                LDSM4(Ah[mf], aRow + mf * (16 * 128) + gh);
                LDSM4(Al[mf], aRow + mf * (16 * 128) + gl);
            }
            #pragma unroll
            for (int g = 0; g < 2; ++g) {
                LDSM4(Bh[g], bRow + g * (16 * 128) + gh);
                LDSM4(Bl[g], bRow + g * (16 * 128) + gl);
            }
            #pragma unroll
            for (int mf = 0; mf < 4; ++mf)
                #pragma unroll
                for (int nf = 0; nf < 4; ++nf) {
                    const int g = nf >> 1, w = nf & 1;
                    MMA16816(acc[mf][nf], Ah[mf], Bh[g][w], Bh[g][w + 2]);   // hi*hi
                    MMA16816(acc[mf][nf], Al[mf], Bh[g][w], Bh[g][w + 2]);   // lo*hi
                    MMA16816(acc[mf][nf], Ah[mf], Bl[g][w], Bl[g][w + 2]);   // hi*lo
                }
        }

        __syncthreads();   // all warps done with stage s before refill
        if (tid == 0 && c + 2 < 32) {
            mbar_expect(MBAR + 8 * s, 2 * TILE_BYTES);
            bulk_g2s(su + SOFF_A + s * TILE_BYTES, Ag + (size_t)(c + 2) * TILE_BYTES, TILE_BYTES, MBAR + 8 * s);
            bulk_g2s(su + SOFF_B + s * TILE_BYTES, Bg + (size_t)(c + 2) * TILE_BYTES, TILE_BYTES, MBAR + 8 * s);
        }
    }

    // epilogue: spline + store
    #pragma unroll
    for (int mf = 0; mf < 4; ++mf) {
        const int row0 = mw + mf * 16 + (lane >> 2);
        const size_t g0 = (size_t)(by * 128 + row0) * NN + bx * 128;
        const size_t g1 = g0 + 8 * NN;
        #pragma unroll
        for (int nf = 0; nf < 4; ++nf) {
            const int cl = nw + nf * 8 + 2 * (lane & 3);
            const float* q0 = &cps[cl * 35];
            const float* q1 = &cps[(cl + 1) * 35];
            float2 o0, o1;
            o0.x = spline_eval(acc[mf][nf].x, q0);
            o0.y = spline_eval(acc[mf][nf].y, q1);
            o1.x = spline_eval(acc[mf][nf].z, q0);
            o1.y = spline_eval(acc[mf][nf].w, q1);
            *reinterpret_cast<float2*>(out + g0 + cl) = o0;
            *reinterpret_cast<float2*>(out + g1 + cl) = o1;
        }
    }
}

extern "C" void kernel_launch(void* const* d_in, const int* in_sizes, int n_in,
                              void* d_out, int out_size)
{
    const float* X  = (const float*)d_in[0];
    const float* W  = (const float*)d_in[1];
    const float* CP = (const float*)d_in[2];
    float* out = (float*)d_out;

    cudaFuncSetAttribute(gemm_spline, cudaFuncAttributeMaxDynamicSharedMemorySize, SMEM_TOTAL);

    convert_fused<<<A_BLOCKS + B_BLOCKS, 256>>>(X, W);

    dim3 grid(NN / 128, MM / 128);   // (8, 128)
    gemm_spline<<<grid, 256, SMEM_TOTAL>>>(CP, out);
}

// round 9
// speedup vs baseline: 1.5589x; 1.0413x over previous
#include <cuda_runtime.h>
#include <cuda_fp16.h>
#include <cstdint>

#define MM 16384
#define DD 1024
#define NN 1024
#define KCP 34

// Chunk-contiguous, XOR-swizzled split-fp16 operands (see R8 layout comment).
__device__ __half A3_buf[(size_t)MM * 2 * DD];   // 64 MB
__device__ __half B3_buf[(size_t)NN * 2 * DD];   // 4 MB

__device__ __forceinline__ uint32_t s2u(const void* p) {
    uint32_t a;
    asm("{ .reg .u64 t; cvta.to.shared.u64 t, %1; cvt.u32.u64 %0, t; }" : "=r"(a) : "l"(p));
    return a;
}

#define LDSM4(r, a) \
    asm volatile("ldmatrix.sync.aligned.m8n8.x4.shared.b16 {%0,%1,%2,%3}, [%4];" \
                 : "=r"((r)[0]), "=r"((r)[1]), "=r"((r)[2]), "=r"((r)[3]) : "r"(a))

// NOTE: not volatile — pure register op; lets ptxas interleave HMMAs with later LDSMs.
#define MMA16816(c, a, b0, b1) \
    asm("mma.sync.aligned.m16n8k16.row.col.f32.f16.f16.f32 " \
        "{%0,%1,%2,%3}, {%4,%5,%6,%7}, {%8,%9}, {%0,%1,%2,%3};" \
        : "+f"((c).x), "+f"((c).y), "+f"((c).z), "+f"((c).w) \
        : "r"((a)[0]), "r"((a)[1]), "r"((a)[2]), "r"((a)[3]), "r"(b0), "r"(b1))

// ---------------- fused convert kernel ----------------
#define A_BLOCKS 32768
#define B_BLOCKS 4096

__global__ __launch_bounds__(256) void convert_fused(const float* __restrict__ X,
                                                     const float* __restrict__ W)
{
    int b = blockIdx.x;
    if (b < A_BLOCKS) {
        int t = b * 256 + threadIdx.x;
        int m = t >> 9;
        int k = (t & 511) * 2;
        float2 v = *reinterpret_cast<const float2*>(X + (size_t)m * DD + k);
        __half h0 = __float2half_rn(v.x);
        __half h1 = __float2half_rn(v.y);
        __half l0 = __float2half_rn(v.x - __half2float(h0));
        __half l1 = __float2half_rn(v.y - __half2float(h1));
        int tile = m >> 7, r = m & 127, kb = k >> 5;
        char* base = reinterpret_cast<char*>(A3_buf + ((size_t)(tile * 32 + kb)) * 8192);
        int gh = (k & 31) >> 3;
        int xk = r & 7;
        int woff = (k & 7) * 2;
        uint32_t offh = (uint32_t)(r * 128 + ((gh ^ xk) * 16) + woff);
        uint32_t offl = (uint32_t)(r * 128 + (((gh + 4) ^ xk) * 16) + woff);
        __half2 hh; hh.x = h0; hh.y = h1;
        __half2 ll; ll.x = l0; ll.y = l1;
        *reinterpret_cast<__half2*>(base + offh) = hh;
        *reinterpret_cast<__half2*>(base + offl) = ll;
    } else {
        int t = (b - A_BLOCKS) * 256 + threadIdx.x;
        int k = t >> 10;
        int n = t & 1023;
        float v = W[(size_t)k * NN + n];
        __half h = __float2half_rn(v);
        __half l = __float2half_rn(v - __half2float(h));
        int tile = n >> 7, r = n & 127, kb = k >> 5;
        char* base = reinterpret_cast<char*>(B3_buf + ((size_t)(tile * 32 + kb)) * 8192);
        int gh = (k & 31) >> 3;
        int xk = r & 7;
        int woff = (k & 7) * 2;
        *reinterpret_cast<__half*>(base + r * 128 + ((gh ^ xk) * 16) + woff)       = h;
        *reinterpret_cast<__half*>(base + r * 128 + (((gh + 4) ^ xk) * 16) + woff) = l;
    }
}

// ---------------- fused GEMM + spline ----------------
// SMEM: cps 17920 | 2 A stages 16KB | 2 B stages 16KB | mbarriers
#define TILE_BYTES  16384
#define SOFF_A      17920
#define SOFF_B      (17920 + 2 * TILE_BYTES)
#define SOFF_MBAR   (17920 + 4 * TILE_BYTES)          // full[2] @ +0,+8 ; empty[2] @ +16,+24
#define SMEM_TOTAL  (17920 + 4 * TILE_BYTES + 64)

__device__ __forceinline__ float spline_eval(float s, const float* __restrict__ q)
{
    float t = s * 4.0f;
    float u = t - floorf(t);
    float pf = floorf((s + 4.0f) * 3.75f + 1.0f);
    if (s <= -4.0f) pf = 1.0f;
    if (s >=  4.0f) pf = 31.0f;
    int p0 = (int)pf;
    p0 = max(1, min(31, p0));
    float Q0 = q[p0 - 1];
    float Q1 = q[p0];
    float Q2 = q[p0 + 1];
    float Q3 = q[p0 + 2];
    float c3 = 3.0f * (Q1 - Q2) + (Q3 - Q0);
    float c2 = 2.0f * Q0 - 5.0f * Q1 + 4.0f * Q2 - Q3;
    float c1 = Q2 - Q0;
    float c0 = 2.0f * Q1;
    return 0.5f * (((c3 * u + c2) * u + c1) * u + c0);
}

__device__ __forceinline__ void mbar_init(uint32_t mbar, uint32_t cnt) {
    asm volatile("mbarrier.init.shared.b64 [%0], %1;" :: "r"(mbar), "r"(cnt) : "memory");
}
__device__ __forceinline__ void mbar_expect(uint32_t mbar, uint32_t bytes) {
    asm volatile("mbarrier.arrive.expect_tx.shared.b64 _, [%0], %1;" :: "r"(mbar), "r"(bytes) : "memory");
}
__device__ __forceinline__ void mbar_arrive(uint32_t mbar) {
    asm volatile("mbarrier.arrive.shared.b64 _, [%0];" :: "r"(mbar) : "memory");
}
__device__ __forceinline__ void mbar_wait_acq(uint32_t mbar, uint32_t parity) {
    asm volatile(
        "{\n\t.reg .pred P;\n\t"
        "LW%=:\n\t"
        "mbarrier.try_wait.parity.acquire.cta.shared::cta.b64 P, [%0], %1, 0x989680;\n\t"
        "@P bra.uni LD%=;\n\t"
        "bra.uni LW%=;\n\t"
        "LD%=:\n\t}"
        :: "r"(mbar), "r"(parity) : "memory");
}
__device__ __forceinline__ void mbar_wait_rlx(uint32_t mbar, uint32_t parity) {
    asm volatile(
        "{\n\t.reg .pred P;\n\t"
        "LW%=:\n\t"
        "mbarrier.try_wait.parity.relaxed.cta.shared::cta.b64 P, [%0], %1, 0x989680;\n\t"
        "@P bra.uni LD%=;\n\t"
        "bra.uni LW%=;\n\t"
        "LD%=:\n\t}"
        :: "r"(mbar), "r"(parity) : "memory");
}
__device__ __forceinline__ void bulk_g2s(uint32_t dst, const void* src, uint32_t bytes, uint32_t mbar) {
    asm volatile("cp.async.bulk.shared::cluster.global.mbarrier::complete_tx::bytes [%0], [%1], %2, [%3];"
                 :: "r"(dst), "l"(src), "r"(bytes), "r"(mbar) : "memory");
}

__global__ __launch_bounds__(256, 2) void gemm_spline(const float* __restrict__ CP,
                                                      float* __restrict__ out)
{
    extern __shared__ char smem[];
    float* cps = reinterpret_cast<float*>(smem);
    const uint32_t su = s2u(smem);
    const uint32_t FULL  = su + SOFF_MBAR;        // +8*s
    const uint32_t EMPTY = su + SOFF_MBAR + 16;   // +8*s

    const int tid  = threadIdx.x;
    const int lane = tid & 31;
    const int wid  = tid >> 5;
    const int bx = blockIdx.x;
    const int by = blockIdx.y;

    const char* Ag = reinterpret_cast<const char*>(A3_buf) + (size_t)by * 32 * TILE_BYTES;
    const char* Bg = reinterpret_cast<const char*>(B3_buf) + (size_t)bx * 32 * TILE_BYTES;

    if (tid == 0) {
        mbar_init(FULL + 0, 1);
        mbar_init(FULL + 8, 1);
        mbar_init(EMPTY + 0, 8);
        mbar_init(EMPTY + 8, 8);
        asm volatile("fence.proxy.async;" ::: "memory");
        #pragma unroll
        for (int s = 0; s < 2; ++s) {
            mbar_expect(FULL + 8 * s, 2 * TILE_BYTES);
            bulk_g2s(su + SOFF_A + s * TILE_BYTES, Ag + (size_t)s * TILE_BYTES, TILE_BYTES, FULL + 8 * s);
            bulk_g2s(su + SOFF_B + s * TILE_BYTES, Bg + (size_t)s * TILE_BYTES, TILE_BYTES, FULL + 8 * s);
        }
    }

    for (int i = tid; i < 128 * KCP; i += 256) {
        int c = i / KCP, k = i - c * KCP;
        cps[c * 35 + k] = CP[(size_t)(bx * 128 + c) * KCP + k];
    }
    __syncthreads();   // mbarrier init + cps visible

    float4 acc[4][4];
    #pragma unroll
    for (int i = 0; i < 4; ++i)
        #pragma unroll
        for (int j = 0; j < 4; ++j)
            acc[i][j] = make_float4(0.f, 0.f, 0.f, 0.f);

    const int mw = (wid >> 2) * 64;
    const int nw = (wid & 3) * 32;
    const int lrow = lane & 15;
    const int lcol = lane >> 4;
    const int xk = lrow & 7;
    // Hoisted swizzled granule offsets: gh/gl for ks=0,1
    const uint32_t g_h[2] = { (uint32_t)(((0 + lcol) ^ xk) * 16), (uint32_t)(((2 + lcol) ^ xk) * 16) };
    const uint32_t g_l[2] = { (uint32_t)(((4 + lcol) ^ xk) * 16), (uint32_t)(((6 + lcol) ^ xk) * 16) };
    const uint32_t aRow0 = su + SOFF_A + (mw + lrow) * 128;
    const uint32_t bRow0 = su + SOFF_B + (nw + lrow) * 128;

    #pragma unroll 1
    for (int c = 0; c < 32; ++c) {
        const int s = c & 1;
        mbar_wait_acq(FULL + 8 * s, (c >> 1) & 1);

        const uint32_t aRow = aRow0 + s * TILE_BYTES;
        const uint32_t bRow = bRow0 + s * TILE_BYTES;

        #pragma unroll
        for (int ks = 0; ks < 2; ++ks) {
            uint32_t Ah[4][4], Al[4][4], Bh[2][4], Bl[2][4];
            #pragma unroll
            for (int mf = 0; mf < 4; ++mf) {
                LDSM4(Ah[mf], aRow + mf * (16 * 128) + g_h[ks]);
                LDSM4(Al[mf], aRow + mf * (16 * 128) + g_l[ks]);
            }
            #pragma unroll
            for (int g = 0; g < 2; ++g) {
                LDSM4(Bh[g], bRow + g * (16 * 128) + g_h[ks]);
                LDSM4(Bl[g], bRow + g * (16 * 128) + g_l[ks]);
            }
            #pragma unroll
            for (int mf = 0; mf < 4; ++mf)
                #pragma unroll
                for (int nf = 0; nf < 4; ++nf) {
                    const int g = nf >> 1, w = nf & 1;
                    MMA16816(acc[mf][nf], Ah[mf], Bh[g][w], Bh[g][w + 2]);   // hi*hi
                    MMA16816(acc[mf][nf], Al[mf], Bh[g][w], Bh[g][w + 2]);   // lo*hi
                    MMA16816(acc[mf][nf], Ah[mf], Bl[g][w], Bl[g][w + 2]);   // hi*lo
                }
        }

        // Per-warp arrive: stage s consumed by this warp (LDSM data already in regs).
        if (lane == 0) mbar_arrive(EMPTY + 8 * s);

        // Producer: refill stage s with chunk c+2 once all 8 warps arrived.
        if (tid == 0 && c + 2 < 32) {
            mbar_wait_rlx(EMPTY + 8 * s, (c >> 1) & 1);
            mbar_expect(FULL + 8 * s, 2 * TILE_BYTES);
            bulk_g2s(su + SOFF_A + s * TILE_BYTES, Ag + (size_t)(c + 2) * TILE_BYTES, TILE_BYTES, FULL + 8 * s);
            bulk_g2s(su + SOFF_B + s * TILE_BYTES, Bg + (size_t)(c + 2) * TILE_BYTES, TILE_BYTES, FULL + 8 * s);
        }
    }

    // epilogue: spline + store
    #pragma unroll
    for (int mf = 0; mf < 4; ++mf) {
        const int row0 = mw + mf * 16 + (lane >> 2);
        const size_t g0 = (size_t)(by * 128 + row0) * NN + bx * 128;
        const size_t g1 = g0 + 8 * NN;
        #pragma unroll
        for (int nf = 0; nf < 4; ++nf) {
            const int cl = nw + nf * 8 + 2 * (lane & 3);
            const float* q0 = &cps[cl * 35];
            const float* q1 = &cps[(cl + 1) * 35];
            float2 o0, o1;
            o0.x = spline_eval(acc[mf][nf].x, q0);
            o0.y = spline_eval(acc[mf][nf].y, q1);
            o1.x = spline_eval(acc[mf][nf].z, q0);
            o1.y = spline_eval(acc[mf][nf].w, q1);
            *reinterpret_cast<float2*>(out + g0 + cl) = o0;
            *reinterpret_cast<float2*>(out + g1 + cl) = o1;
        }
    }
}

extern "C" void kernel_launch(void* const* d_in, const int* in_sizes, int n_in,
                              void* d_out, int out_size)
{
    const float* X  = (const float*)d_in[0];
    const float* W  = (const float*)d_in[1];
    const float* CP = (const float*)d_in[2];
    float* out = (float*)d_out;

    cudaFuncSetAttribute(gemm_spline, cudaFuncAttributeMaxDynamicSharedMemorySize, SMEM_TOTAL);

    convert_fused<<<A_BLOCKS + B_BLOCKS, 256>>>(X, W);

    dim3 grid(NN / 128, MM / 128);   // (8, 128)
    gemm_spline<<<grid, 256, SMEM_TOTAL>>>(CP, out);
}

// round 10
// speedup vs baseline: 1.6836x; 1.0800x over previous
#include <cuda_runtime.h>
#include <cuda_fp16.h>
#include <cstdint>

#define MM 16384
#define DD 1024
#define NN 1024
#define KCP 34

// Chunk-contiguous, XOR-swizzled split-fp16 operands.
// tile = 128 rows x 128B; row r granule g (16B) at (g ^ (r&7))*16; g0..3 hi, g4..7 lo.
__device__ __half A3_buf[(size_t)MM * 2 * DD];   // 64 MB
__device__ __half B3_buf[(size_t)NN * 2 * DD];   // 4 MB

__device__ __forceinline__ uint32_t s2u(const void* p) {
    uint32_t a;
    asm("{ .reg .u64 t; cvta.to.shared.u64 t, %1; cvt.u32.u64 %0, t; }" : "=r"(a) : "l"(p));
    return a;
}

#define LDSM4(r, a) \
    asm volatile("ldmatrix.sync.aligned.m8n8.x4.shared.b16 {%0,%1,%2,%3}, [%4];" \
                 : "=r"((r)[0]), "=r"((r)[1]), "=r"((r)[2]), "=r"((r)[3]) : "r"(a))

#define MMA16816(c, a, b0, b1) \
    asm("mma.sync.aligned.m16n8k16.row.col.f32.f16.f16.f32 " \
        "{%0,%1,%2,%3}, {%4,%5,%6,%7}, {%8,%9}, {%0,%1,%2,%3};" \
        : "+f"((c).x), "+f"((c).y), "+f"((c).z), "+f"((c).w) \
        : "r"((a)[0]), "r"((a)[1]), "r"((a)[2]), "r"((a)[3]), "r"(b0), "r"(b1))

// ---------------- vectorized convert kernels ----------------
// One thread = one 16B granule pair (8 k-values -> 16B hi + 16B lo).

__device__ __forceinline__ void split8(const float4 f0, const float4 f1,
                                       uint4& hi, uint4& lo)
{
    const float v[8] = {f0.x, f0.y, f0.z, f0.w, f1.x, f1.y, f1.z, f1.w};
    __half h[8], l[8];
    #pragma unroll
    for (int i = 0; i < 8; ++i) {
        h[i] = __float2half_rn(v[i]);
        l[i] = __float2half_rn(v[i] - __half2float(h[i]));
    }
    hi = *reinterpret_cast<const uint4*>(h);
    lo = *reinterpret_cast<const uint4*>(l);
}

__global__ __launch_bounds__(256) void convert_A(const float* __restrict__ X)
{
    int t = blockIdx.x * blockDim.x + threadIdx.x;   // MM*128 threads
    int m  = t >> 7;
    int j  = t & 127;
    int kb = j >> 2;
    int g  = j & 3;
    const float4* src = reinterpret_cast<const float4*>(X + (size_t)m * DD + kb * 32 + g * 8);
    uint4 hi, lo;
    split8(src[0], src[1], hi, lo);
    int tile = m >> 7, r = m & 127, xk = r & 7;
    char* base = reinterpret_cast<char*>(A3_buf) + ((size_t)(tile * 32 + kb)) * 16384 + r * 128;
    *reinterpret_cast<uint4*>(base + ((g ^ xk) * 16))       = hi;
    *reinterpret_cast<uint4*>(base + (((g + 4) ^ xk) * 16)) = lo;
}

__global__ __launch_bounds__(256) void convert_B(const float* __restrict__ W)
{
    int t = blockIdx.x * blockDim.x + threadIdx.x;   // NN*128 threads
    int n    = t & 1023;
    int rest = t >> 10;
    int kb = rest >> 2;
    int g  = rest & 3;
    int k0 = kb * 32 + g * 8;
    float v[8];
    #pragma unroll
    for (int i = 0; i < 8; ++i)
        v[i] = W[(size_t)(k0 + i) * NN + n];          // warp-coalesced along n
    __half h[8], l[8];
    #pragma unroll
    for (int i = 0; i < 8; ++i) {
        h[i] = __float2half_rn(v[i]);
        l[i] = __float2half_rn(v[i] - __half2float(h[i]));
    }
    int tile = n >> 7, r = n & 127, xk = r & 7;
    char* base = reinterpret_cast<char*>(B3_buf) + ((size_t)(tile * 32 + kb)) * 16384 + r * 128;
    *reinterpret_cast<uint4*>(base + ((g ^ xk) * 16))       = *reinterpret_cast<const uint4*>(h);
    *reinterpret_cast<uint4*>(base + (((g + 4) ^ xk) * 16)) = *reinterpret_cast<const uint4*>(l);
}

// ---------------- fused GEMM + spline ----------------
#define TILE_BYTES  16384
#define SOFF_A      17920
#define SOFF_B      (17920 + 2 * TILE_BYTES)
#define SOFF_MBAR   (17920 + 4 * TILE_BYTES)
#define SMEM_TOTAL  (17920 + 4 * TILE_BYTES + 64)

__device__ __forceinline__ float spline_eval(float s, const float* __restrict__ q)
{
    float t = s * 4.0f;
    float u = t - floorf(t);
    float pf = floorf((s + 4.0f) * 3.75f + 1.0f);
    if (s <= -4.0f) pf = 1.0f;
    if (s >=  4.0f) pf = 31.0f;
    int p0 = (int)pf;
    p0 = max(1, min(31, p0));
    float Q0 = q[p0 - 1];
    float Q1 = q[p0];
    float Q2 = q[p0 + 1];
    float Q3 = q[p0 + 2];
    float c3 = 3.0f * (Q1 - Q2) + (Q3 - Q0);
    float c2 = 2.0f * Q0 - 5.0f * Q1 + 4.0f * Q2 - Q3;
    float c1 = Q2 - Q0;
    float c0 = 2.0f * Q1;
    return 0.5f * (((c3 * u + c2) * u + c1) * u + c0);
}

__device__ __forceinline__ void mbar_init(uint32_t mbar, uint32_t cnt) {
    asm volatile("mbarrier.init.shared.b64 [%0], %1;" :: "r"(mbar), "r"(cnt) : "memory");
}
__device__ __forceinline__ void mbar_expect(uint32_t mbar, uint32_t bytes) {
    asm volatile("mbarrier.arrive.expect_tx.shared.b64 _, [%0], %1;" :: "r"(mbar), "r"(bytes) : "memory");
}
__device__ __forceinline__ void mbar_arrive(uint32_t mbar) {
    asm volatile("mbarrier.arrive.shared.b64 _, [%0];" :: "r"(mbar) : "memory");
}
__device__ __forceinline__ void mbar_wait_acq(uint32_t mbar, uint32_t parity) {
    asm volatile(
        "{\n\t.reg .pred P;\n\t"
        "LW%=:\n\t"
        "mbarrier.try_wait.parity.acquire.cta.shared::cta.b64 P, [%0], %1, 0x989680;\n\t"
        "@P bra.uni LD%=;\n\t"
        "bra.uni LW%=;\n\t"
        "LD%=:\n\t}"
        :: "r"(mbar), "r"(parity) : "memory");
}
__device__ __forceinline__ void mbar_wait_rlx(uint32_t mbar, uint32_t parity) {
    asm volatile(
        "{\n\t.reg .pred P;\n\t"
        "LW%=:\n\t"
        "mbarrier.try_wait.parity.relaxed.cta.shared::cta.b64 P, [%0], %1, 0x989680;\n\t"
        "@P bra.uni LD%=;\n\t"
        "bra.uni LW%=;\n\t"
        "LD%=:\n\t}"
        :: "r"(mbar), "r"(parity) : "memory");
}
__device__ __forceinline__ void bulk_g2s(uint32_t dst, const void* src, uint32_t bytes, uint32_t mbar) {
    asm volatile("cp.async.bulk.shared::cluster.global.mbarrier::complete_tx::bytes [%0], [%1], %2, [%3];"
                 :: "r"(dst), "l"(src), "r"(bytes), "r"(mbar) : "memory");
}

__global__ __launch_bounds__(256, 2) void gemm_spline(const float* __restrict__ CP,
                                                      float* __restrict__ out)
{
    extern __shared__ char smem[];
    float* cps = reinterpret_cast<float*>(smem);
    const uint32_t su = s2u(smem);
    const uint32_t FULL  = su + SOFF_MBAR;
    const uint32_t EMPTY = su + SOFF_MBAR + 16;

    const int tid  = threadIdx.x;
    const int lane = tid & 31;
    const int wid  = tid >> 5;
    const int bx = blockIdx.x;
    const int by = blockIdx.y;

    const char* Ag = reinterpret_cast<const char*>(A3_buf) + (size_t)by * 32 * TILE_BYTES;
    const char* Bg = reinterpret_cast<const char*>(B3_buf) + (size_t)bx * 32 * TILE_BYTES;

    if (tid == 0) {
        mbar_init(FULL + 0, 1);
        mbar_init(FULL + 8, 1);
        mbar_init(EMPTY + 0, 8);
        mbar_init(EMPTY + 8, 8);
        asm volatile("fence.proxy.async;" ::: "memory");
        #pragma unroll
        for (int s = 0; s < 2; ++s) {
            mbar_expect(FULL + 8 * s, 2 * TILE_BYTES);
            bulk_g2s(su + SOFF_A + s * TILE_BYTES, Ag + (size_t)s * TILE_BYTES, TILE_BYTES, FULL + 8 * s);
            bulk_g2s(su + SOFF_B + s * TILE_BYTES, Bg + (size_t)s * TILE_BYTES, TILE_BYTES, FULL + 8 * s);
        }
    }

    for (int i = tid; i < 128 * KCP; i += 256) {
        int c = i / KCP, k = i - c * KCP;
        cps[c * 35 + k] = CP[(size_t)(bx * 128 + c) * KCP + k];
    }
    __syncthreads();

    float4 acc[4][4];
    #pragma unroll
    for (int i = 0; i < 4; ++i)
        #pragma unroll
        for (int j = 0; j < 4; ++j)
            acc[i][j] = make_float4(0.f, 0.f, 0.f, 0.f);

    const int mw = (wid >> 2) * 64;
    const int nw = (wid & 3) * 32;
    const int lrow = lane & 15;
    const int lcol = lane >> 4;
    const int xk = lrow & 7;
    const uint32_t g_h[2] = { (uint32_t)(((0 + lcol) ^ xk) * 16), (uint32_t)(((2 + lcol) ^ xk) * 16) };
    const uint32_t g_l[2] = { (uint32_t)(((4 + lcol) ^ xk) * 16), (uint32_t)(((6 + lcol) ^ xk) * 16) };
    const uint32_t aRowS[2] = { su + SOFF_A + (mw + lrow) * 128,
                                su + SOFF_A + TILE_BYTES + (mw + lrow) * 128 };
    const uint32_t bRowS[2] = { su + SOFF_B + (nw + lrow) * 128,
                                su + SOFF_B + TILE_BYTES + (nw + lrow) * 128 };

    // One chunk: wait FULL, LDSM both ks (arrive EMPTY after last LDSM batch,
    // before the MMAs), compute, then producer refills.
    #define DO_CHUNK(S, CIDX, PH)                                                        \
    {                                                                                    \
        mbar_wait_acq(FULL + 8 * (S), (PH));                                             \
        const uint32_t aRow = aRowS[(S)];                                                \
        const uint32_t bRow = bRowS[(S)];                                                \
        uint32_t Ah0[4][4], Al0[4][4], Bh0[2][4], Bl0[2][4];                             \
        _Pragma("unroll")                                                                \
        for (int mf = 0; mf < 4; ++mf) {                                                 \
            LDSM4(Ah0[mf], aRow + mf * (16 * 128) + g_h[0]);                             \
            LDSM4(Al0[mf], aRow + mf * (16 * 128) + g_l[0]);                             \
        }                                                                                \
        _Pragma("unroll")                                                                \
        for (int g = 0; g < 2; ++g) {                                                    \
            LDSM4(Bh0[g], bRow + g * (16 * 128) + g_h[0]);                               \
            LDSM4(Bl0[g], bRow + g * (16 * 128) + g_l[0]);                               \
        }                                                                                \
        _Pragma("unroll")                                                                \
        for (int mf = 0; mf < 4; ++mf)                                                   \
            _Pragma("unroll")                                                            \
            for (int nf = 0; nf < 4; ++nf) {                                             \
                const int g = nf >> 1, w = nf & 1;                                       \
                MMA16816(acc[mf][nf], Ah0[mf], Bh0[g][w], Bh0[g][w + 2]);                \
                MMA16816(acc[mf][nf], Al0[mf], Bh0[g][w], Bh0[g][w + 2]);                \
                MMA16816(acc[mf][nf], Ah0[mf], Bl0[g][w], Bl0[g][w + 2]);                \
            }                                                                            \
        uint32_t Ah1[4][4], Al1[4][4], Bh1[2][4], Bl1[2][4];                             \
        _Pragma("unroll")                                                                \
        for (int mf = 0; mf < 4; ++mf) {                                                 \
            LDSM4(Ah1[mf], aRow + mf * (16 * 128) + g_h[1]);                             \
            LDSM4(Al1[mf], aRow + mf * (16 * 128) + g_l[1]);                             \
        }                                                                                \
        _Pragma("unroll")                                                                \
        for (int g = 0; g < 2; ++g) {                                                    \
            LDSM4(Bh1[g], bRow + g * (16 * 128) + g_h[1]);                               \
            LDSM4(Bl1[g], bRow + g * (16 * 128) + g_l[1]);                               \
        }                                                                                \
        if (lane == 0) mbar_arrive(EMPTY + 8 * (S));   /* smem reads all issued */       \
        _Pragma("unroll")                                                                \
        for (int mf = 0; mf < 4; ++mf)                                                   \
            _Pragma("unroll")                                                            \
            for (int nf = 0; nf < 4; ++nf) {                                             \
                const int g = nf >> 1, w = nf & 1;                                       \
                MMA16816(acc[mf][nf], Ah1[mf], Bh1[g][w], Bh1[g][w + 2]);                \
                MMA16816(acc[mf][nf], Al1[mf], Bh1[g][w], Bh1[g][w + 2]);                \
                MMA16816(acc[mf][nf], Ah1[mf], Bl1[g][w], Bl1[g][w + 2]);                \
            }                                                                            \
        if (tid == 0 && (CIDX) + 2 < 32) {                                               \
            mbar_wait_rlx(EMPTY + 8 * (S), (PH));                                        \
            mbar_expect(FULL + 8 * (S), 2 * TILE_BYTES);                                 \
            bulk_g2s(su + SOFF_A + (S) * TILE_BYTES,                                     \
                     Ag + (size_t)((CIDX) + 2) * TILE_BYTES, TILE_BYTES, FULL + 8 * (S));\
            bulk_g2s(su + SOFF_B + (S) * TILE_BYTES,                                     \
                     Bg + (size_t)((CIDX) + 2) * TILE_BYTES, TILE_BYTES, FULL + 8 * (S));\
        }                                                                                \
    }

    #pragma unroll 1
    for (int p = 0; p < 16; ++p) {
        const uint32_t ph = (uint32_t)(p & 1);
        DO_CHUNK(0, 2 * p,     ph)
        DO_CHUNK(1, 2 * p + 1, ph)
    }
    #undef DO_CHUNK

    // epilogue: spline + store
    #pragma unroll
    for (int mf = 0; mf < 4; ++mf) {
        const int row0 = mw + mf * 16 + (lane >> 2);
        const size_t g0 = (size_t)(by * 128 + row0) * NN + bx * 128;
        const size_t g1 = g0 + 8 * NN;
        #pragma unroll
        for (int nf = 0; nf < 4; ++nf) {
            const int cl = nw + nf * 8 + 2 * (lane & 3);
            const float* q0 = &cps[cl * 35];
            const float* q1 = &cps[(cl + 1) * 35];
            float2 o0, o1;
            o0.x = spline_eval(acc[mf][nf].x, q0);
            o0.y = spline_eval(acc[mf][nf].y, q1);
            o1.x = spline_eval(acc[mf][nf].z, q0);
            o1.y = spline_eval(acc[mf][nf].w, q1);
            *reinterpret_cast<float2*>(out + g0 + cl) = o0;
            *reinterpret_cast<float2*>(out + g1 + cl) = o1;
        }
    }
}

extern "C" void kernel_launch(void* const* d_in, const int* in_sizes, int n_in,
                              void* d_out, int out_size)
{
    const float* X  = (const float*)d_in[0];
    const float* W  = (const float*)d_in[1];
    const float* CP = (const float*)d_in[2];
    float* out = (float*)d_out;

    cudaFuncSetAttribute(gemm_spline, cudaFuncAttributeMaxDynamicSharedMemorySize, SMEM_TOTAL);

    convert_A<<<(MM * 128) / 256, 256>>>(X);
    convert_B<<<(NN * 128) / 256, 256>>>(W);

    dim3 grid(NN / 128, MM / 128);   // (8, 128)
    gemm_spline<<<grid, 256, SMEM_TOTAL>>>(CP, out);
}